// round 12
// baseline (speedup 1.0000x reference)
#include <cuda_runtime.h>
#include <cuda_fp16.h>
#include <cstdint>

#define HW 128
#define KSZ 255
#define NTHR 256
#define NPC 2

// smem: tables 2 bufs (whp@k*2048, wwp@k*2048+1024), planes @ 4096 + k*32768
#define OFF_P0 4096
#define SMEM_TOTAL (4096 + 65536)

// K-major fp16 plane: rows x 256B; 16B chunks XOR-swizzled by row&7.
__device__ __forceinline__ uint32_t off_rk(int r, int k) {
    return (uint32_t)(r * 256 + ((((k >> 3) ^ (r & 7)) << 4) | ((k & 7) << 1)));
}

__device__ __forceinline__ uint32_t s2u(const void* p) {
    uint32_t a;
    asm("{ .reg .u64 t; cvta.to.shared.u64 t, %1; cvt.u32.u64 %0, t; }" : "=r"(a) : "l"(p));
    return a;
}

__device__ __forceinline__ void ldsm4(uint32_t* r, uint32_t a) {
    asm volatile("ldmatrix.sync.aligned.m8n8.x4.shared.b16 {%0,%1,%2,%3},[%4];"
                 : "=r"(r[0]), "=r"(r[1]), "=r"(r[2]), "=r"(r[3]) : "r"(a));
}

__device__ __forceinline__ void mma_f16(float* d, uint32_t a0, uint32_t a1, uint32_t a2,
                                        uint32_t a3, uint32_t b0, uint32_t b1) {
    asm volatile(
        "mma.sync.aligned.m16n8k16.row.col.f32.f16.f16.f32 "
        "{%0,%1,%2,%3},{%4,%5,%6,%7},{%8,%9},{%0,%1,%2,%3};"
        : "+f"(d[0]), "+f"(d[1]), "+f"(d[2]), "+f"(d[3])
        : "r"(a0), "r"(a1), "r"(a2), "r"(a3), "r"(b0), "r"(b1));
}

__device__ __forceinline__ uint32_t pack2(float a, float b) {
    __half2 h = __floats2half2_rn(a, b);
    return *(uint32_t*)&h;
}

__device__ __forceinline__ uint32_t lds32(uint32_t addr) {
    uint32_t v;
    asm volatile("ld.shared.b32 %0, [%1];" : "=r"(v) : "r"(addr));
    return v;
}

extern "C" __global__ void __launch_bounds__(NTHR, 2)
conv_mma_kernel(const float* __restrict__ x,
                const float* __restrict__ wh, const float* __restrict__ bh,
                const float* __restrict__ ww, const float* __restrict__ bw,
                float* __restrict__ out) {
    extern __shared__ __align__(1024) char smem[];
    uint32_t sb = s2u(smem);
    int t = threadIdx.x, lane = t & 31, wid = t >> 5;
    int img0 = blockIdx.x * NPC;
    int c0 = img0 & 255;

    int w = t & 127, ihalf = t >> 7;
    int g = lane >> 2, tt2 = (lane & 3) * 2;
    int mbase = wid * 16;
    int nB = lane & 7, khB = (lane & 15) >> 3, tB = lane >> 4;

    // Tables for img0 (buf 0)
    if (t < KSZ - 1) {
        const float* wp = wh + c0 * KSZ;
        *(uint32_t*)(smem + 4 * t) = pack2(wp[t], wp[t + 1]);
        wp = ww + c0 * KSZ;
        *(uint32_t*)(smem + 1024 + 4 * t) = pack2(wp[t], wp[t + 1]);
    }
    // Convert img0 -> plane0 (blocking, first image only)
    {
        const float* xp = x + ((size_t)img0 << 14) + w;
#pragma unroll
        for (int blk = 0; blk < 8; blk++) {
            int i0 = ihalf * 64 + blk * 8;
            uint32_t q[4];
#pragma unroll
            for (int j = 0; j < 4; j++)
                q[j] = pack2(xp[(i0 + 2 * j) * HW], xp[(i0 + 2 * j + 1) * HW]);
            *(uint4*)(smem + OFF_P0 + off_rk(w, i0)) = *(uint4*)q;
        }
    }
    float bhv = bh[c0], bwv = bw[c0];
    __syncthreads();

    float cv[3][8];
    float nbh = 0.f, nbw = 0.f, tw0 = 0.f, tw1 = 0.f, tw2 = 0.f, tw3 = 0.f;

#pragma unroll
    for (int k = 0; k < NPC; k++) {
        const bool nxt = (k + 1 < NPC);
        int img = img0 + k;
        size_t base = (size_t)img << 14;
        uint32_t pln = sb + OFF_P0 + (uint32_t)k * 32768u;
        uint32_t npln = sb + OFF_P0 + (uint32_t)(k ^ 1) * 32768u;
        uint32_t pwh = sb + (uint32_t)k * 2048u;
        uint32_t pww = pwh + 1024u;

        // ---- Stage 1: Y[h][w] = Toep(wh) @ X, rows mbase..mbase+15. ----
        float d1[16][4];
#pragma unroll
        for (int tn = 0; tn < 16; tn++)
#pragma unroll
            for (int q = 0; q < 4; q++) d1[tn][q] = bhv;
        {
            int ib1 = 127 + tt2 - g - mbase;
            uint32_t W1a = lds32(pwh + 4u * (uint32_t)(ib1 - 8));
            uint32_t W1b = lds32(pwh + 4u * (uint32_t)(ib1));
            uint32_t W1c = lds32(pwh + 4u * (uint32_t)(ib1 + 8));
            uint32_t bRow = (uint32_t)(8 * tB + nB) * 256;
#pragma unroll
            for (int kk = 0; kk < 8; kk++) {
                if (kk) {
                    W1a = W1c;
                    W1b = lds32(pwh + 4u * (uint32_t)(ib1 + 16 * kk));
                    W1c = lds32(pwh + 4u * (uint32_t)(ib1 + 16 * kk + 8));
                }
                uint32_t bx = (uint32_t)(((2 * kk + khB) ^ nB) << 4);
                uint32_t bb[8][4];
#pragma unroll
                for (int gg = 0; gg < 8; gg++)
                    ldsm4(bb[gg], pln + bRow + (uint32_t)gg * 4096 + bx);
#pragma unroll
                for (int tn = 0; tn < 16; tn++)
                    mma_f16(d1[tn], W1b, W1a, W1c, W1b,
                            bb[tn >> 1][(tn & 1) * 2], bb[tn >> 1][(tn & 1) * 2 + 1]);
            }
        }

        // In-register handoff: Y accums -> stage-2 A fragments.
        uint32_t fA[8][4];
#pragma unroll
        for (int q = 0; q < 8; q++) {
            fA[q][0] = pack2(d1[2 * q][0], d1[2 * q][1]);
            fA[q][1] = pack2(d1[2 * q][2], d1[2 * q][3]);
            fA[q][2] = pack2(d1[2 * q + 1][0], d1[2 * q + 1][1]);
            fA[q][3] = pack2(d1[2 * q + 1][2], d1[2 * q + 1][3]);
        }

        // Prefetch next-image weights/biases into regs (LDG, L2-friendly).
        const float* xn = x + ((size_t)(img + 1) << 14) + w;
        if (nxt) {
            int cn = (img + 1) & 255;
            if (t < KSZ - 1) {
                const float* wpn = wh + cn * KSZ;
                tw0 = wpn[t]; tw1 = wpn[t + 1];
                wpn = ww + cn * KSZ;
                tw2 = wpn[t]; tw3 = wpn[t + 1];
            }
            nbh = bh[cn]; nbw = bw[cn];
        }

        // ---- Stage 2 in two n-halves; convert of next image pipelined in. ----
        int ib2 = 7 + tt2 - g;
#pragma unroll
        for (int h = 0; h < 2; h++) {
            int b = h ? 0 : 8;
            float d2[8][4];
#pragma unroll
            for (int tn = 0; tn < 8; tn++)
#pragma unroll
                for (int q = 0; q < 4; q++) d2[tn][q] = bwv;

            uint32_t R[9];
#pragma unroll
            for (int i = 0; i < 9; i++)
                R[i] = lds32(pww + 4u * (uint32_t)(ib2 + 8 * (b + i)));

#pragma unroll
            for (int q = 0; q < 8; q++) {
                if (q) {
#pragma unroll
                    for (int i = 0; i < 7; i++) R[i] = R[i + 2];
                    R[7] = lds32(pww + 4u * (uint32_t)(ib2 + 8 * (2 * q + b + 7)));
                    R[8] = lds32(pww + 4u * (uint32_t)(ib2 + 8 * (2 * q + b + 8)));
                }
                if (nxt) {
                    int it = h * 8 + q;
                    if (it >= 3 && it <= 10) {       // pack + STS blk it-3
                        int bpk = it - 3;
                        int i0 = ihalf * 64 + bpk * 8;
                        uint32_t qq[4];
#pragma unroll
                        for (int j = 0; j < 4; j++)
                            qq[j] = pack2(cv[bpk % 3][2 * j], cv[bpk % 3][2 * j + 1]);
                        *(uint4*)(smem + (npln - sb) + off_rk(w, i0)) = *(uint4*)qq;
                    }
                    if (it < 8) {                    // issue blk it LDGs
                        int i0 = ihalf * 64 + it * 8;
#pragma unroll
                        for (int j = 0; j < 4; j++) {
                            cv[it % 3][2 * j] = xn[(i0 + 2 * j) * HW];
                            cv[it % 3][2 * j + 1] = xn[(i0 + 2 * j + 1) * HW];
                        }
                    }
                }
#pragma unroll
                for (int tn = 0; tn < 8; tn++)
                    mma_f16(d2[tn], fA[q][0], fA[q][1], fA[q][2], fA[q][3],
                            R[7 - tn], R[8 - tn]);
            }

            if (h == 0 && nxt && t < KSZ - 1) {      // next tables -> buf k^1
                *(uint32_t*)(smem + (k ^ 1) * 2048 + 4 * t) = pack2(tw0, tw1);
                *(uint32_t*)(smem + (k ^ 1) * 2048 + 1024 + 4 * t) = pack2(tw2, tw3);
            }

            // Store this half's columns.
            {
                int r0 = mbase + g;
#pragma unroll
                for (int tn = 0; tn < 8; tn++) {
                    int cc = 64 * h + 8 * tn + tt2;
                    *(float2*)(out + base + (size_t)r0 * HW + cc) =
                        make_float2(d2[tn][0], d2[tn][1]);
                    *(float2*)(out + base + (size_t)(r0 + 8) * HW + cc) =
                        make_float2(d2[tn][2], d2[tn][3]);
                }
            }
        }

        if (nxt) { bhv = nbh; bwv = nbw; }
        __syncthreads();
    }
}

extern "C" void kernel_launch(void* const* d_in, const int* in_sizes, int n_in,
                              void* d_out, int out_size) {
    const float* x  = (const float*)d_in[0];
    const float* wh = (const float*)d_in[1];
    const float* bh = (const float*)d_in[2];
    const float* ww = (const float*)d_in[3];
    const float* bw = (const float*)d_in[4];
    float* out = (float*)d_out;

    int nimg = in_sizes[0] >> 14;
    int grid = nimg / NPC;
    cudaFuncSetAttribute(conv_mma_kernel,
                         cudaFuncAttributeMaxDynamicSharedMemorySize, SMEM_TOTAL);
    conv_mma_kernel<<<grid, NTHR, SMEM_TOTAL>>>(x, wh, bh, ww, bw, out);
}